// round 2
// baseline (speedup 1.0000x reference)
#include <cuda_runtime.h>
#include <math.h>

#define BB 64
#define NN 16384
#define MM 128
#define CC 1024
#define EPSV 1e-16f

// ---- scratch (device globals; no allocation allowed) ----
__device__ float g_S[BB * NN];          // 4 MB: beta*sim, then exp values
__device__ float g_k[BB * MM];
__device__ float g_kn[BB];
__device__ float g_beta[BB], g_gate[BB], g_gamma[BB];
__device__ float g_shift[BB][3];
__device__ unsigned int g_maxbits[BB];  // ordered-uint float max
__device__ float g_Z[BB];               // softmax denominator
__device__ float g_WZ[BB];              // sharpen denominator

__device__ __forceinline__ unsigned int ford(float f) {
    unsigned int u = __float_as_uint(f);
    return (u >> 31) ? ~u : (u | 0x80000000u);
}
__device__ __forceinline__ float funord(unsigned int u) {
    return (u >> 31) ? __uint_as_float(u ^ 0x80000000u) : __uint_as_float(~u);
}
__device__ __forceinline__ float softplus_f(float x) {
    return (x > 20.f) ? x : log1pf(expf(x));
}

// ---- 1. init accumulators + zero read_vec output region ----
__global__ void k_init(float* __restrict__ out_read) {
    int i = blockIdx.x * blockDim.x + threadIdx.x;
    if (i < BB) {
        g_maxbits[i] = ford(-INFINITY);
        g_Z[i] = 0.f;
        g_WZ[i] = 0.f;
    }
    if (i < BB * MM) out_read[i] = 0.f;
}

// ---- 2. projections: k=tanh(ctrl@Wk+bk), beta/gate/gamma/shift heads ----
__global__ void k_proj(const float* __restrict__ ctrl,
                       const float* __restrict__ key_w, const float* __restrict__ key_b,
                       const float* __restrict__ beta_w, const float* __restrict__ beta_b,
                       const float* __restrict__ gate_w, const float* __restrict__ gate_b,
                       const float* __restrict__ shift_w, const float* __restrict__ shift_b,
                       const float* __restrict__ gamma_w, const float* __restrict__ gamma_b) {
    __shared__ float sc[CC];
    __shared__ float red[MM];
    __shared__ float r6[6][MM];
    int b = blockIdx.x, t = threadIdx.x;
    for (int i = t; i < CC; i += MM) sc[i] = ctrl[b * CC + i];
    __syncthreads();

    // key column t
    float acc = 0.f;
    #pragma unroll 8
    for (int c = 0; c < CC; c++) acc += sc[c] * key_w[c * MM + t];
    float kt = tanhf(acc + key_b[t]);
    g_k[b * MM + t] = kt;

    red[t] = kt * kt;
    __syncthreads();
    for (int s = 64; s > 0; s >>= 1) {
        if (t < s) red[t] += red[t + s];
        __syncthreads();
    }
    if (t == 0) g_kn[b] = sqrtf(red[0]);

    // 6 scalar dots
    float a0 = 0, a1 = 0, a2 = 0, s0 = 0, s1 = 0, s2 = 0;
    for (int c = t; c < CC; c += MM) {
        float x = sc[c];
        a0 += x * beta_w[c];
        a1 += x * gate_w[c];
        a2 += x * gamma_w[c];
        s0 += x * shift_w[c * 3 + 0];
        s1 += x * shift_w[c * 3 + 1];
        s2 += x * shift_w[c * 3 + 2];
    }
    r6[0][t] = a0; r6[1][t] = a1; r6[2][t] = a2;
    r6[3][t] = s0; r6[4][t] = s1; r6[5][t] = s2;
    __syncthreads();
    for (int s = 64; s > 0; s >>= 1) {
        if (t < s)
            #pragma unroll
            for (int j = 0; j < 6; j++) r6[j][t] += r6[j][t + s];
        __syncthreads();
    }
    if (t == 0) {
        g_beta[b]  = softplus_f(r6[0][0] + beta_b[0]);
        g_gate[b]  = 1.f / (1.f + expf(-(r6[1][0] + gate_b[0])));
        g_gamma[b] = 1.f + softplus_f(r6[2][0] + gamma_b[0]);
        float v0 = r6[3][0] + shift_b[0];
        float v1 = r6[4][0] + shift_b[1];
        float v2 = r6[5][0] + shift_b[2];
        float mx = fmaxf(v0, fmaxf(v1, v2));
        float e0 = expf(v0 - mx), e1 = expf(v1 - mx), e2 = expf(v2 - mx);
        float inv = 1.f / (e0 + e1 + e2);
        g_shift[b][0] = e0 * inv;
        g_shift[b][1] = e1 * inv;
        g_shift[b][2] = e2 * inv;
    }
}

// ---- 3. pass 1 over memory: beta*cosine-sim, track max ----
__global__ void __launch_bounds__(256) k_sim(const float* __restrict__ mem) {
    int b = blockIdx.y;
    int tid = threadIdx.x, warp = tid >> 5, lane = tid & 31;
    __shared__ float sk[MM];
    if (tid < MM) sk[tid] = g_k[b * MM + tid];
    __syncthreads();
    float k0 = sk[lane * 4 + 0], k1 = sk[lane * 4 + 1];
    float k2 = sk[lane * 4 + 2], k3 = sk[lane * 4 + 3];
    float beta = g_beta[b], kn = g_kn[b];
    float lmax = -INFINITY;
    int base = blockIdx.x * 256;
    const float4* mp = (const float4*)(mem + (size_t)b * NN * MM);

    #pragma unroll 4
    for (int i = 0; i < 32; i++) {
        int n = base + i * 8 + warp;
        float4 v = mp[(size_t)n * 32 + lane];
        float dot = k0 * v.x + k1 * v.y + k2 * v.z + k3 * v.w;
        float nrm = v.x * v.x + v.y * v.y + v.z * v.z + v.w * v.w;
        #pragma unroll
        for (int off = 16; off > 0; off >>= 1) {
            dot += __shfl_down_sync(0xffffffffu, dot, off);
            nrm += __shfl_down_sync(0xffffffffu, nrm, off);
        }
        if (lane == 0) {
            float s = beta * dot / (kn * sqrtf(nrm) + EPSV);
            g_S[b * NN + n] = s;
            lmax = fmaxf(lmax, s);
        }
    }
    if (lane == 0) atomicMax(&g_maxbits[b], ford(lmax));
}

// ---- 4. exp(s - max), accumulate Z ----
__global__ void __launch_bounds__(256) k_exp() {
    __shared__ float red[256];
    int b = blockIdx.y, t = threadIdx.x;
    float mx = funord(g_maxbits[b]);
    float4* Sp = (float4*)(g_S + b * NN);
    int idx = blockIdx.x * 256 + t;
    float4 v = Sp[idx];
    v.x = expf(v.x - mx); v.y = expf(v.y - mx);
    v.z = expf(v.z - mx); v.w = expf(v.w - mx);
    Sp[idx] = v;
    red[t] = v.x + v.y + v.z + v.w;
    __syncthreads();
    for (int s = 128; s > 0; s >>= 1) {
        if (t < s) red[t] += red[t + s];
        __syncthreads();
    }
    if (t == 0) atomicAdd(&g_Z[b], red[0]);
}

// ---- 5. gated interp + circular shift + sharpen power; write wp to d_out ----
__global__ void __launch_bounds__(256) k_w(const float* __restrict__ pw,
                                           float* __restrict__ out_w) {
    __shared__ float red[256];
    int b = blockIdx.y, t = threadIdx.x;
    float gate = g_gate[b], og = 1.f - gate;
    float invZ = 1.f / g_Z[b];
    float s0 = g_shift[b][0], s1 = g_shift[b][1], s2 = g_shift[b][2];
    float gamma = g_gamma[b];
    const float* Sb = g_S + (size_t)b * NN;
    const float* pwb = pw + (size_t)b * NN;
    int n0 = blockIdx.x * 1024 + t * 4;

    float w[6];
    #pragma unroll
    for (int j = 0; j < 6; j++) {
        int nn = (n0 - 1 + j) & (NN - 1);
        w[j] = gate * Sb[nn] * invZ + og * pwb[nn];
    }
    float lsum = 0.f;
    #pragma unroll
    for (int j = 0; j < 4; j++) {
        float ws = s0 * w[j] + s1 * w[j + 1] + s2 * w[j + 2];
        float wp = powf(ws, gamma);
        out_w[(size_t)b * NN + n0 + j] = wp;
        lsum += wp;
    }
    red[t] = lsum;
    __syncthreads();
    for (int s = 128; s > 0; s >>= 1) {
        if (t < s) red[t] += red[t + s];
        __syncthreads();
    }
    if (t == 0) atomicAdd(&g_WZ[b], red[0]);
}

// ---- 6. pass 2 over memory: normalize weights in-place + weighted read ----
__global__ void __launch_bounds__(128) k_read(const float* __restrict__ mem,
                                              float* __restrict__ out) {
    __shared__ float sw[256];
    int b = blockIdx.y, t = threadIdx.x;
    float inv = 1.f / (g_WZ[b] + EPSV);
    int base = blockIdx.x * 256;
    float* wout = out + (size_t)b * NN;

    #pragma unroll
    for (int j = 0; j < 2; j++) {
        int n = base + j * 128 + t;
        float w = wout[n] * inv;
        wout[n] = w;
        sw[j * 128 + t] = w;
    }
    __syncthreads();

    const float* mb = mem + ((size_t)b * NN + base) * MM + t;
    float acc = 0.f;
    #pragma unroll 4
    for (int i = 0; i < 256; i++) {
        acc += sw[i] * mb[(size_t)i * MM];
    }
    atomicAdd(&out[(size_t)BB * NN + b * MM + t], acc);
}

extern "C" void kernel_launch(void* const* d_in, const int* in_sizes, int n_in,
                              void* d_out, int out_size) {
    const float* ctrl    = (const float*)d_in[0];
    const float* pw      = (const float*)d_in[1];
    const float* mem     = (const float*)d_in[2];
    const float* key_w   = (const float*)d_in[3];
    const float* key_b   = (const float*)d_in[4];
    const float* beta_w  = (const float*)d_in[5];
    const float* beta_b  = (const float*)d_in[6];
    const float* gate_w  = (const float*)d_in[7];
    const float* gate_b  = (const float*)d_in[8];
    const float* shift_w = (const float*)d_in[9];
    const float* shift_b = (const float*)d_in[10];
    const float* gamma_w = (const float*)d_in[11];
    const float* gamma_b = (const float*)d_in[12];
    // d_in[13..16] = erase_w/b, add_w/b — unused by the output, skipped.
    float* out = (float*)d_out;
    float* out_read = out + (size_t)BB * NN;

    k_init<<<(BB * MM + 255) / 256, 256>>>(out_read);
    k_proj<<<BB, MM>>>(ctrl, key_w, key_b, beta_w, beta_b, gate_w, gate_b,
                       shift_w, shift_b, gamma_w, gamma_b);
    {
        dim3 g(NN / 256, BB);
        k_sim<<<g, 256>>>(mem);
    }
    {
        dim3 g(NN / 1024, BB);
        k_exp<<<g, 256>>>();
        k_w<<<g, 256>>>(pw, out);
    }
    {
        dim3 g(NN / 256, BB);
        k_read<<<g, 128>>>(mem, out);
    }
}